// round 6
// baseline (speedup 1.0000x reference)
#include <cuda_runtime.h>
#include <cuda_bf16.h>
#include <math.h>
#include <stdint.h>

#define NB 64
#define TT 512
#define NI 256
#define NH 1024
#define NOISEF 0.1f
#define NKS 8             // k-slices of 128
#define NJT 16            // j-tiles of 64
#define NBLK 128

// ---- static device scratch ----
__device__ float g_h32[2][NB * NH];         // fp32 hidden state [b][j]
__device__ unsigned int g_hpk[NB * NH];     // packed bf16 hi<<16|lo of h [b][k]
__device__ float g_part[NKS][NH * NB];      // split-K slabs, layout [j][b]
__device__ float g_alpha[NH];
__device__ float g_wt[NI * NH];             // transposed in_w for proj (f32)
__device__ __nv_bfloat16 g_wthi[NH * NH];   // [j][k] = bf16_hi(W[k][j])
__device__ __nv_bfloat16 g_wtlo[NH * NH];   // [j][k] = residual
__device__ int g_cnt;
__device__ int g_done;

// smem layout (272B-padded rows of 128 bf16 for conflict-free ldmatrix)
#define SM_WHI 0
#define SM_WLO 17408
#define SM_BHI 34816
#define SM_BLO 52224
#define SM_TOTAL 69632
#define ROWB 272

static __device__ __forceinline__ uint32_t smem_u32(const void* p) {
    uint32_t a;
    asm("{ .reg .u64 t; cvta.to.shared.u64 t, %1; cvt.u32.u64 %0, t; }" : "=r"(a) : "l"(p));
    return a;
}

#define LDSM4(r, a)                                                             \
    asm volatile("ldmatrix.sync.aligned.m8n8.x4.shared.b16 {%0,%1,%2,%3}, [%4];" \
        : "=r"((r)[0]), "=r"((r)[1]), "=r"((r)[2]), "=r"((r)[3]) : "r"(a))

#define MMA16816(d, a, b0, b1)                                                  \
    asm volatile("mma.sync.aligned.m16n8k16.row.col.f32.bf16.bf16.f32 "         \
        "{%0,%1,%2,%3}, {%4,%5,%6,%7}, {%8,%9}, {%0,%1,%2,%3};"                 \
        : "+f"((d)[0]), "+f"((d)[1]), "+f"((d)[2]), "+f"((d)[3])                \
        : "r"((a)[0]), "r"((a)[1]), "r"((a)[2]), "r"((a)[3]), "r"(b0), "r"(b1))

// ---- f32x2 helpers for proj ----
__device__ __forceinline__ unsigned long long pk2(float a, float b) {
    unsigned long long r;
    asm("mov.b64 %0, {%1, %2};" : "=l"(r) : "r"(__float_as_uint(a)), "r"(__float_as_uint(b)));
    return r;
}
__device__ __forceinline__ float2 upk2(unsigned long long v) {
    unsigned int lo, hi;
    asm("mov.b64 {%0, %1}, %2;" : "=r"(lo), "=r"(hi) : "l"(v));
    return make_float2(__uint_as_float(lo), __uint_as_float(hi));
}
__device__ __forceinline__ unsigned long long ffma2(unsigned long long a,
                                                    unsigned long long b,
                                                    unsigned long long c) {
    unsigned long long d;
    asm("fma.rn.f32x2 %0, %1, %2, %3;" : "=l"(d) : "l"(a), "l"(b), "l"(c));
    return d;
}

__global__ void init_kernel(const float* __restrict__ taus) {
    int idx = blockIdx.x * blockDim.x + threadIdx.x;
    if (idx < NB * NH) { g_h32[0][idx] = 0.0f; g_hpk[idx] = 0u; }
    if (idx < NH) {
        float s = 1.0f / (1.0f + expf(-taus[idx]));
        g_alpha[idx] = 10.0f / (s * 90.0f + 10.0f);
    }
    if (idx == 0) { g_cnt = 0; g_done = 0; }
}

// transpose in_w [H][I] -> g_wt [I][H] (f32, for proj)
__global__ void transpose_kernel(const float* __restrict__ w) {
    __shared__ float t[32][33];
    int bi = blockIdx.x * 32;
    int bh = blockIdx.y * 32;
    int tx = threadIdx.x, ty = threadIdx.y;
    for (int i = ty; i < 32; i += 8) t[i][tx] = w[(bh + i) * NI + bi + tx];
    __syncthreads();
    for (int i = ty; i < 32; i += 8) g_wt[(bi + i) * NH + bh + tx] = t[tx][i];
}

// W [k][j] -> g_wthi/g_wtlo [j][k] bf16 split
__global__ void wsplit_kernel(const float* __restrict__ W) {
    __shared__ float t[32][33];
    int bk = blockIdx.x * 32;
    int bj = blockIdx.y * 32;
    int tx = threadIdx.x, ty = threadIdx.y;
    for (int i = ty; i < 32; i += 8) t[i][tx] = W[(bk + i) * NH + bj + tx];
    __syncthreads();
    for (int i = ty; i < 32; i += 8) {
        float v = t[tx][i];                       // W[bk+tx][bj+i]
        __nv_bfloat16 hi = __float2bfloat16(v);
        float r = v - __bfloat162float(hi);
        g_wthi[(bj + i) * NH + bk + tx] = hi;
        g_wtlo[(bj + i) * NH + bk + tx] = __float2bfloat16(r);
    }
}

// ---------------------------------------------------------------------------
// Input projection (FFMA2, unchanged from R4)
// ---------------------------------------------------------------------------
__global__ void __launch_bounds__(256) proj_kernel(
    const float* __restrict__ x, const float* __restrict__ bias,
    const float* __restrict__ eps, float* __restrict__ out)
{
    __shared__ float xs[64][20];
    __shared__ float ws[16][68];
    const int tid = threadIdx.x;
    const int rg = tid >> 4, cg = tid & 15;
    const int r4 = rg << 2, c4 = cg << 2;
    const int j0 = blockIdx.x * 64;
    const int r0 = blockIdx.y * 64;
    const int lr = tid >> 2, lk = (tid & 3) << 2;
    const int wk = tid >> 4, wj = (tid & 15) << 2;

    unsigned long long acc[4][2];
#pragma unroll
    for (int i = 0; i < 4; i++) { acc[i][0] = 0ull; acc[i][1] = 0ull; }

    for (int k0 = 0; k0 < NI; k0 += 16) {
        *(float4*)&xs[lr][lk] = *(const float4*)(x + (r0 + lr) * NI + k0 + lk);
        *(float4*)&ws[wk][wj] = *(const float4*)(g_wt + (k0 + wk) * NH + j0 + wj);
        __syncthreads();
#pragma unroll
        for (int k = 0; k < 16; k += 4) {
            ulonglong2 b0 = *(const ulonglong2*)&ws[k + 0][c4];
            ulonglong2 b1 = *(const ulonglong2*)&ws[k + 1][c4];
            ulonglong2 b2 = *(const ulonglong2*)&ws[k + 2][c4];
            ulonglong2 b3 = *(const ulonglong2*)&ws[k + 3][c4];
#pragma unroll
            for (int i = 0; i < 4; i++) {
                float4 a = *(const float4*)&xs[r4 + i][k];
                unsigned long long p;
                p = pk2(a.x, a.x); acc[i][0] = ffma2(p, b0.x, acc[i][0]); acc[i][1] = ffma2(p, b0.y, acc[i][1]);
                p = pk2(a.y, a.y); acc[i][0] = ffma2(p, b1.x, acc[i][0]); acc[i][1] = ffma2(p, b1.y, acc[i][1]);
                p = pk2(a.z, a.z); acc[i][0] = ffma2(p, b2.x, acc[i][0]); acc[i][1] = ffma2(p, b2.y, acc[i][1]);
                p = pk2(a.w, a.w); acc[i][0] = ffma2(p, b3.x, acc[i][0]); acc[i][1] = ffma2(p, b3.y, acc[i][1]);
            }
        }
        __syncthreads();
    }

    float4 bi = *(const float4*)(bias + j0 + c4);
#pragma unroll
    for (int i = 0; i < 4; i++) {
        int r = r0 + r4 + i;
        int off = r * NH + j0 + c4;
        float4 ev = *(const float4*)(eps + off);
        float2 lo = upk2(acc[i][0]);
        float2 hi = upk2(acc[i][1]);
        float4 o;
        o.x = lo.x + bi.x + NOISEF * ev.x;
        o.y = lo.y + bi.y + NOISEF * ev.y;
        o.z = hi.x + bi.z + NOISEF * ev.z;
        o.w = hi.y + bi.w + NOISEF * ev.w;
        *(float4*)(out + off) = o;
    }
}

// ---------------------------------------------------------------------------
// Persistent scan: 128 blocks (jt, ks). HMMA split-bf16 GEMM.
// D[j0..j0+63][b] partial over k-slice; slab exchange; distributed epilogue.
// ---------------------------------------------------------------------------
__global__ void __launch_bounds__(256) scan_kernel(float* __restrict__ out)
{
    extern __shared__ char smem[];
    const uint32_t sb = smem_u32(smem);
    const int tid = threadIdx.x;
    const int l = tid & 31, w = tid >> 5;
    const int jt = blockIdx.x & 15;
    const int ks = blockIdx.x >> 4;
    const int j0 = jt * 64;
    const int k0 = ks * 128;

    // Load W^T hi/lo tile [64 j][128 k] into padded smem (once)
    {
        int r = tid >> 2, c = tid & 3;
        const uint4* sh = (const uint4*)(g_wthi + (j0 + r) * NH + k0) + c * 4;
        const uint4* sl = (const uint4*)(g_wtlo + (j0 + r) * NH + k0) + c * 4;
        char* dh = smem + SM_WHI + r * ROWB + c * 64;
        char* dl = smem + SM_WLO + r * ROWB + c * 64;
#pragma unroll
        for (int i = 0; i < 4; i++) {
            *(uint4*)(dh + i * 16) = sh[i];
            *(uint4*)(dl + i * 16) = sl[i];
        }
    }

    // ldmatrix per-lane addresses
    const int wm = (w & 3) * 16;    // j offset of warp
    const int wn = (w >> 2) * 32;   // b offset of warp (4 ntiles of 8)
    const uint32_t aHi = sb + SM_WHI + (wm + (l & 15)) * ROWB + (l >> 4) * 16;
    const uint32_t aLo = aHi + (SM_WLO - SM_WHI);
    const uint32_t brow = wn + ((l >> 4) << 3) + (l & 7);
    const uint32_t boff = ((l >> 3) & 1) * 16;
    const uint32_t b0Hi = sb + SM_BHI + brow * ROWB + boff;
    const uint32_t b1Hi = b0Hi + 16 * ROWB;
    const uint32_t b0Lo = b0Hi + (SM_BLO - SM_BHI);
    const uint32_t b1Lo = b1Hi + (SM_BLO - SM_BHI);

    // slab-store coords
    const int sj0 = j0 + wm + (l >> 2);
    const int sb0 = wn + 2 * (l & 3);

    // epilogue mapping: j = bid*8 + warp, b = 2*(lane)
    const int ej = blockIdx.x * 8 + w;
    const int eb = l * 2;
    const float alf = g_alpha[ej];

    // staging coords
    const int stb = tid >> 2, stc = tid & 3;
    const uint4* hsrc = (const uint4*)(g_hpk + stb * NH + k0) + stc * 8;
    char* dBh = smem + SM_BHI + stb * ROWB + stc * 64;
    char* dBl = smem + SM_BLO + stb * ROWB + stc * 64;

    __syncthreads();

    for (int t = 0; t < TT; t++) {
        // rendezvous 1: all epilogues of step t-1 done (h_pk ready, slabs free)
        if (t > 0) {
            if (tid == 0) { while (__ldcg(&g_done) < NBLK * t) __nanosleep(32); }
            __syncthreads();
        }

        // stage h slice: unpack h_pk -> bf16 hi/lo smem rows
#pragma unroll
        for (int i = 0; i < 8; i++) {
            uint4 v = __ldcg(hsrc + i);
            uint32_t h0 = __byte_perm(v.x, v.y, 0x7632);
            uint32_t l0 = __byte_perm(v.x, v.y, 0x5410);
            uint32_t h1 = __byte_perm(v.z, v.w, 0x7632);
            uint32_t l1 = __byte_perm(v.z, v.w, 0x5410);
            *(uint2*)(dBh + i * 8) = make_uint2(h0, h1);
            *(uint2*)(dBl + i * 8) = make_uint2(l0, l1);
        }
        __syncthreads();

        // GEMM: 8 k-steps of 16, split-bf16 (3 products), HMMA
        float acc[4][4];
#pragma unroll
        for (int n = 0; n < 4; n++)
#pragma unroll
            for (int i = 0; i < 4; i++) acc[n][i] = 0.0f;

#pragma unroll
        for (int kk = 0; kk < 8; kk++) {
            const uint32_t off = kk * 32;
            uint32_t ah[4], al4[4], bh0[4], bh1[4], bl0[4], bl1[4];
            LDSM4(ah, aHi + off);
            LDSM4(al4, aLo + off);
            LDSM4(bh0, b0Hi + off);
            LDSM4(bh1, b1Hi + off);
            LDSM4(bl0, b0Lo + off);
            LDSM4(bl1, b1Lo + off);
            MMA16816(acc[0], ah, bh0[0], bh0[1]);
            MMA16816(acc[1], ah, bh0[2], bh0[3]);
            MMA16816(acc[2], ah, bh1[0], bh1[1]);
            MMA16816(acc[3], ah, bh1[2], bh1[3]);
            MMA16816(acc[0], ah, bl0[0], bl0[1]);
            MMA16816(acc[1], ah, bl0[2], bl0[3]);
            MMA16816(acc[2], ah, bl1[0], bl1[1]);
            MMA16816(acc[3], ah, bl1[2], bl1[3]);
            MMA16816(acc[0], al4, bh0[0], bh0[1]);
            MMA16816(acc[1], al4, bh0[2], bh0[3]);
            MMA16816(acc[2], al4, bh1[0], bh1[1]);
            MMA16816(acc[3], al4, bh1[2], bh1[3]);
        }

        // store slab [j][b] (float2 per fragment row-pair)
        {
            float* part = g_part[ks];
#pragma unroll
            for (int n = 0; n < 4; n++) {
                int bcol = sb0 + n * 8;
                *(float2*)(part + sj0 * 64 + bcol) = make_float2(acc[n][0], acc[n][1]);
                *(float2*)(part + (sj0 + 8) * 64 + bcol) = make_float2(acc[n][2], acc[n][3]);
            }
        }

        // prefetch epilogue operands (independent of slabs)
        const float pre0 = out[((long)eb * TT + t) * NH + ej];
        const float pre1 = out[((long)(eb + 1) * TT + t) * NH + ej];
        const float hv0 = g_h32[t & 1][eb * NH + ej];
        const float hv1 = g_h32[t & 1][(eb + 1) * NH + ej];

        __threadfence();
        __syncthreads();
        if (tid == 0) {
            atomicAdd(&g_cnt, 1);
            while (__ldcg(&g_cnt) < NBLK * (t + 1)) __nanosleep(32);
        }
        __syncthreads();

        // distributed epilogue: j=ej, b=eb..eb+1; coalesced slab reads
        {
            float2 s = __ldcg((const float2*)(g_part[0] + ej * 64 + eb));
#pragma unroll
            for (int q = 1; q < NKS; q++) {
                float2 v = __ldcg((const float2*)(g_part[q] + ej * 64 + eb));
                s.x += v.x; s.y += v.y;
            }
            float hn0 = (1.0f - alf) * hv0 + alf * tanhf(pre0 + s.x);
            float hn1 = (1.0f - alf) * hv1 + alf * tanhf(pre1 + s.y);
            out[((long)eb * TT + t) * NH + ej] = hn0;
            out[((long)(eb + 1) * TT + t) * NH + ej] = hn1;
            float* ho = g_h32[(t + 1) & 1];
            ho[eb * NH + ej] = hn0;
            ho[(eb + 1) * NH + ej] = hn1;
            // packed bf16 hi/lo for next step's GEMM
            __nv_bfloat16 bh_ = __float2bfloat16(hn0);
            __nv_bfloat16 bl_ = __float2bfloat16(hn0 - __bfloat162float(bh_));
            g_hpk[eb * NH + ej] =
                ((uint32_t)__bfloat16_as_ushort(bh_) << 16) | __bfloat16_as_ushort(bl_);
            bh_ = __float2bfloat16(hn1);
            bl_ = __float2bfloat16(hn1 - __bfloat162float(bh_));
            g_hpk[(eb + 1) * NH + ej] =
                ((uint32_t)__bfloat16_as_ushort(bh_) << 16) | __bfloat16_as_ushort(bl_);
        }

        __threadfence();
        __syncthreads();
        if (tid == 0) atomicAdd(&g_done, 1);
    }
}

extern "C" void kernel_launch(void* const* d_in, const int* in_sizes, int n_in,
                              void* d_out, int out_size) {
    const float* x    = (const float*)d_in[0];  // [B,T,I]
    const float* eps  = (const float*)d_in[1];  // [B,T,H]
    const float* in_w = (const float*)d_in[2];  // [H,I]
    const float* in_b = (const float*)d_in[3];  // [H]
    const float* W    = (const float*)d_in[4];  // [H,H]
    const float* taus = (const float*)d_in[5];  // [H]
    float* out = (float*)d_out;                 // [B,T,H]

    static int attr_done = 0;
    if (!attr_done) {
        cudaFuncSetAttribute(scan_kernel, cudaFuncAttributeMaxDynamicSharedMemorySize, SM_TOTAL);
        attr_done = 1;
    }

    init_kernel<<<(NB * NH + 255) / 256, 256>>>(taus);
    transpose_kernel<<<dim3(NI / 32, NH / 32), dim3(32, 8)>>>(in_w);
    wsplit_kernel<<<dim3(NH / 32, NH / 32), dim3(32, 8)>>>(W);

    dim3 pgrid(NH / 64, (NB * TT) / 64);
    proj_kernel<<<pgrid, 256>>>(x, in_b, eps, out);

    scan_kernel<<<NBLK, 256, SM_TOTAL>>>(out);
}